// round 12
// baseline (speedup 1.0000x reference)
#include <cuda_runtime.h>

#define NVW   9
#define HSZ   480
#define WSZ   640
#define NPIX  (HSZ*WSZ)
#define GD    96
#define NCELL (GD*GD*GD)
#define MAXN  400000
#define PIXB4 (NPIX/(256*4))   // 300 blocks per view image (4 px/thread)
#define PIXB  (NPIX/256)       // 1200 blocks per view image (1 px/thread)
#define GRIDB (NCELL/256)      // 3456 blocks for voxel grid
#define TMMB  (NVW*PIXB4)      // 2700 target-minmax blocks
#define DMMV  (NPIX/(256*2))   // 600 depth-minmax blocks per view (2 px/thread)

// ==== zero-canonical scratch: .bss zero == canonical empty; consumers   ====
// ==== restore what they consume (g_last by grid, g_dz by final, scalars ====
// ==== by loss; g_grid / g_nrm fully rewritten before every read).       ====
__device__ __align__(16) int                g_last[NCELL];   // idx+1, 0 = empty
__device__ float                            g_grid[NCELL];
__device__ __align__(16) float4             g_nrm[MAXN];     // per-point raw normal
// packed z-buffer: stores ~((zbits<<32)|idx); atomicMax == min over (z,idx); 0 = no hit
__device__ __align__(16) unsigned long long g_dz[NVW*NPIX];
__device__ unsigned int g_dminE[NVW], g_tminE[NVW];  // ~bits of min (atomicMax, 0-canonical)
__device__ unsigned int g_dmax[NVW],  g_tmax[NVW];   // bits of max (vals>=0, 0-canonical)
__device__ float        g_lsum[NVW];
__device__ int          g_vcnt[NVW];

// XLA:CPU dot (no FMA contraction, left-assoc, strict rn): ((p0*m0 + p1*m1) + p2*m2)
__device__ __forceinline__ float dotrow(const float* M, float px, float py, float pz) {
    return __fadd_rn(__fadd_rn(__fmul_rn(px, M[0]), __fmul_rn(py, M[1])),
                     __fmul_rn(pz, M[2]));
}
// u = rn( (f*x)/zs + c ), strict
__device__ __forceinline__ int proj_pix(float f, float c, float x, float zs) {
    return __float2int_rn(__fadd_rn(__fdiv_rn(__fmul_rn(f, x), zs), c));
}

__device__ __forceinline__ void load_view_consts(const float* __restrict__ vm,
                                                 const float* __restrict__ intr,
                                                 float* s_vm, float* s_in) {
    int t = threadIdx.x;
    if (t < NVW * 12) s_vm[t] = vm[(t / 12) * 16 + (t % 12)];   // rows 0..2 of 4x4
    if (t < NVW * 4) {
        int v = t >> 2, k = t & 3;
        int off = (k == 0) ? 0 : (k == 1) ? 5 : (k == 2) ? 2 : 6; // fx,fy,cx,cy
        s_in[t] = intr[v * 16 + off];
    }
    __syncthreads();
}

// ---- L1 fused: [0,projB) scatter ; [projB,..) target-image min/max/count --
__global__ void k_scatter_tmm(const int4* __restrict__ coords,
                              const float* __restrict__ tgt, int n, int projB) {
    if ((int)blockIdx.x < projB) {
        int i = blockIdx.x * blockDim.x + threadIdx.x;
        if (i >= n) return;
        int4 q = coords[i];                    // (.x=0, .y=c1, .z=c2, .w=c3)
        atomicMax(&g_last[(q.w * GD + q.z) * GD + q.y], i + 1);  // last-write-wins
        return;
    }
    int b = blockIdx.x - projB;
    int v = b / PIXB4;
    int p4 = (b % PIXB4) * blockDim.x + threadIdx.x;
    float4 dt = reinterpret_cast<const float4*>(tgt)[v * (NPIX/4) + p4];
    float mnt = fminf(fminf(dt.x, dt.y), fminf(dt.z, dt.w));
    float mxt = fmaxf(fmaxf(dt.x, dt.y), fmaxf(dt.z, dt.w));
    int cnt = (dt.x != 0.f) + (dt.y != 0.f) + (dt.z != 0.f) + (dt.w != 0.f);
    for (int o = 16; o; o >>= 1) {
        mnt = fminf(mnt, __shfl_down_sync(0xffffffffu, mnt, o));
        mxt = fmaxf(mxt, __shfl_down_sync(0xffffffffu, mxt, o));
        cnt += __shfl_down_sync(0xffffffffu, cnt, o);
    }
    __shared__ float smnt[8], smxt[8];
    __shared__ int sc[8];
    int wid = threadIdx.x >> 5, lid = threadIdx.x & 31;
    if (lid == 0) { smnt[wid] = mnt; smxt[wid] = mxt; sc[wid] = cnt; }
    __syncthreads();
    if (threadIdx.x == 0) {
        for (int w = 1; w < 8; w++) {
            mnt = fminf(mnt, smnt[w]); mxt = fmaxf(mxt, smxt[w]); cnt += sc[w];
        }
        atomicMax(&g_tminE[v], ~__float_as_uint(mnt));   // encoded min (0-canonical)
        atomicMax(&g_tmax[v],   __float_as_uint(mxt));
        atomicAdd(&g_vcnt[v], cnt);
    }
}

// -- L2 fused: [0,GRIDB) grid materialize+clean ; [GRIDB,..) project (u64) --
__global__ void k_grid_project(const int4* __restrict__ coords,
                               const float* __restrict__ origin,
                               const float* __restrict__ vm,
                               const float* __restrict__ intr,
                               const float* __restrict__ sdf, int n) {
    if (blockIdx.x < GRIDB) {
        int c = blockIdx.x * blockDim.x + threadIdx.x;
        int idx = g_last[c];
        g_grid[c] = (idx > 0) ? __ldg(&sdf[idx - 1]) : 0.f;
        if (idx > 0) g_last[c] = 0;                     // self-clean (skip if clean)
        return;
    }
    __shared__ float s_vm[NVW * 12];
    __shared__ float s_in[NVW * 4];
    load_view_consts(vm, intr, s_vm, s_in);
    int i = (blockIdx.x - GRIDB) * blockDim.x + threadIdx.x;
    if (i >= n) return;
    int4 q = coords[i];
    float px = __fadd_rn((float)q.w, __ldg(&origin[0]));
    float py = __fadd_rn((float)q.z, __ldg(&origin[1]));
    float pz = __fadd_rn((float)q.y, __ldg(&origin[2]));
    #pragma unroll
    for (int v = 0; v < NVW; v++) {
        const float* M = &s_vm[v * 12];
        float x = __fadd_rn(dotrow(M,     px, py, pz), M[3]);
        float y = __fadd_rn(dotrow(M + 4, px, py, pz), M[7]);
        float z = __fadd_rn(dotrow(M + 8, px, py, pz), M[11]);
        float zs = (fabsf(z) < 1e-6f) ? 1e-6f : z;
        int u = proj_pix(s_in[v*4+0], s_in[v*4+2], x, zs);
        int w = proj_pix(s_in[v*4+1], s_in[v*4+3], y, zs);
        if (z > 0.025f && z < 100.0f && u >= 0 && u < WSZ && w >= 0 && w < HSZ) {
            unsigned long long packed =
                ((unsigned long long)__float_as_uint(z) << 32) | (unsigned)i;
            atomicMax(&g_dz[v * NPIX + w * WSZ + u], ~packed);  // == min (z, idx)
        }
    }
}

// -- L3 fused: [0,normB) per-point raw normals ; [normB,..) depth minmax ----
__global__ void k_nrm_dmm(const int4* __restrict__ coords, int n, int normB) {
    if ((int)blockIdx.x < normB) {
        int i = blockIdx.x * blockDim.x + threadIdx.x;
        if (i >= n) return;
        int4 q = coords[i];
        float na = 0.f, nb = 0.f, nc = 0.f;              // central-diff normal
        if (q.w >= 1 && q.w <= GD-2 && q.z >= 1 && q.z <= GD-2 && q.y >= 1 && q.y <= GD-2) {
            int base = (q.w * GD + q.z) * GD + q.y;
            na = __fsub_rn(g_grid[base + 1],     g_grid[base - 1]);
            nb = __fsub_rn(g_grid[base + GD],    g_grid[base - GD]);
            nc = __fsub_rn(g_grid[base + GD*GD], g_grid[base - GD*GD]);
        }
        g_nrm[i] = make_float4(na, nb, nc, 0.f);
        return;
    }
    int b = blockIdx.x - normB;
    int v = b / DMMV;
    int p2 = (b % DMMV) * blockDim.x + threadIdx.x;
    ulonglong2 raw = reinterpret_cast<const ulonglong2*>(g_dz)[v * (NPIX/2) + p2];
    float d0 = raw.x ? __fmul_rn(__uint_as_float((unsigned)(~raw.x >> 32)), 0.04f) : 0.f;
    float d1 = raw.y ? __fmul_rn(__uint_as_float((unsigned)(~raw.y >> 32)), 0.04f) : 0.f;
    float mnd = fminf(d0, d1);
    float mxd = fmaxf(d0, d1);
    for (int o = 16; o; o >>= 1) {
        mnd = fminf(mnd, __shfl_down_sync(0xffffffffu, mnd, o));
        mxd = fmaxf(mxd, __shfl_down_sync(0xffffffffu, mxd, o));
    }
    __shared__ float smnd[8], smxd[8];
    int wid = threadIdx.x >> 5, lid = threadIdx.x & 31;
    if (lid == 0) { smnd[wid] = mnd; smxd[wid] = mxd; }
    __syncthreads();
    if (threadIdx.x == 0) {
        for (int w = 1; w < 8; w++) { mnd = fminf(mnd, smnd[w]); mxd = fmaxf(mxd, smxd[w]); }
        atomicMax(&g_dminE[v], ~__float_as_uint(mnd));
        atomicMax(&g_dmax[v],   __float_as_uint(mxd));
    }
}

// --- L4: finalize — normalize images + rotate winner normal + loss ---------
__global__ void k_final(const float* __restrict__ vm,
                        const float* __restrict__ tgt, float* __restrict__ out) {
    int v = blockIdx.y;
    __shared__ float s_M[12];
    if (threadIdx.x < 12) s_M[threadIdx.x] = vm[v * 16 + threadIdx.x];  // rows 0..2
    __syncthreads();
    int p = blockIdx.x * blockDim.x + threadIdx.x;
    int gp = v * NPIX + p;
    unsigned long long raw = g_dz[gp];
    bool hit = raw != 0ull;
    unsigned long long packed = ~raw;
    float dimg = hit ? __fmul_rn(__uint_as_float((unsigned)(packed >> 32)), 0.04f) : 0.f;
    float dmn = __uint_as_float(~g_dminE[v]);
    float sd  = __fsub_rn(dimg, dmn);
    float drg = __fsub_rn(__uint_as_float(g_dmax[v]), dmn);
    float dn = (drg != 0.f) ? __fdiv_rn(sd, drg) : sd;
    float dt = tgt[gp];
    float tmn = __uint_as_float(~g_tminE[v]);
    float st  = __fsub_rn(dt, tmn);
    float trg = __fsub_rn(__uint_as_float(g_tmax[v]), tmn);
    float tn = (trg != 0.f) ? __fdiv_rn(st, trg) : st;
    __stcs(&out[1 + gp], dn);                          // streaming: don't pollute L2
    __stcs(&out[1 + NVW * NPIX + gp], tn);
    float* nout = &out[1 + 2 * NVW * NPIX + 3 * gp];
    if (hit) {
        float4 nr = g_nrm[(unsigned)(packed & 0xffffffffu)];   // winner's raw normal
        float rx = dotrow(s_M,     nr.x, nr.y, nr.z);
        float ry = dotrow(s_M + 4, nr.x, nr.y, nr.z);
        float rz = dotrow(s_M + 8, nr.x, nr.y, nr.z);
        float ss = __fadd_rn(__fadd_rn(__fmul_rn(rx, rx), __fmul_rn(ry, ry)),
                             __fmul_rn(rz, rz));
        float len = fmaxf(__fsqrt_rn(ss), 1e-5f);
        __stcs(nout + 0, __fdiv_rn(-rx, len));
        __stcs(nout + 1, __fdiv_rn(-ry, len));
        __stcs(nout + 2, __fdiv_rn(-rz, len));
        g_dz[gp] = 0ull;                               // self-clean
    } else {
        __stcs(nout + 0, 0.f);
        __stcs(nout + 1, 0.f);
        __stcs(nout + 2, 0.f);
    }
    float l = (dt != 0.f) ? fabsf(__fsub_rn(dn, tn)) : 0.f;
    for (int o = 16; o; o >>= 1) l += __shfl_down_sync(0xffffffffu, l, o);
    __shared__ float sl[8];
    int wid = threadIdx.x >> 5, lid = threadIdx.x & 31;
    if (lid == 0) sl[wid] = l;
    __syncthreads();
    if (threadIdx.x == 0) {
        for (int w = 1; w < 8; w++) l += sl[w];
        atomicAdd(&g_lsum[v], l);
    }
}

// ---------------- L5: loss + scalar self-clean ------------------------------
__global__ void k_loss(float* __restrict__ out) {
    if (threadIdx.x == 0) {
        float tot = 0.f;
        for (int v = 0; v < NVW; v++) {
            float c = (float)g_vcnt[v];
            float l = (g_vcnt[v] > 0) ? __fdiv_rn(g_lsum[v], fmaxf(c, 1.f)) : 0.f;
            tot = __fadd_rn(tot, __fdiv_rn(l, 9.0f));   // * WEIGHT(1) / N_VIEWS
            g_lsum[v] = 0.f; g_vcnt[v] = 0;             // self-clean
            g_dminE[v] = 0u; g_tminE[v] = 0u;
            g_dmax[v] = 0u;  g_tmax[v] = 0u;
        }
        out[0] = tot;
    }
}

// ---------------------------------------------------------------------------
extern "C" void kernel_launch(void* const* d_in, const int* in_sizes, int n_in,
                              void* d_out, int out_size) {
    const int4*  coords = (const int4*) d_in[0];
    const float* origin = (const float*)d_in[1];
    const float* sdf    = (const float*)d_in[2];
    // d_in[3] = sdf_target (unused by forward)
    const float* tgt    = (const float*)d_in[4];
    const float* intr   = (const float*)d_in[5];
    const float* vm     = (const float*)d_in[6];
    float* out = (float*)d_out;

    int n = in_sizes[0] / 4;
    if (n > MAXN) n = MAXN;
    const int tb = 256;
    int projB = (n + tb - 1) / tb;

    k_scatter_tmm<<<projB + TMMB, tb>>>(coords, tgt, n, projB);
    k_grid_project<<<GRIDB + projB, tb>>>(coords, origin, vm, intr, sdf, n);
    k_nrm_dmm<<<projB + NVW * DMMV, tb>>>(coords, n, projB);
    dim3 rg(PIXB, NVW);
    k_final<<<rg, tb>>>(vm, tgt, out);
    k_loss<<<1, 32>>>(out);
}

// round 13
// speedup vs baseline: 1.4767x; 1.4767x over previous
#include <cuda_runtime.h>

#define NVW   9
#define HSZ   480
#define WSZ   640
#define NPIX  (HSZ*WSZ)
#define GD    96
#define NCELL (GD*GD*GD)
#define MAXN  400000
#define PIXB4 (NPIX/(256*4))   // 300 blocks per view image (4 px/thread)
#define PIXB  (NPIX/256)       // 1200 blocks per view image (1 px/thread)
#define PIXB2 (NPIX/(256*2))   // 600 blocks per view image (2 px/thread)
#define GRIDB (NCELL/256)      // 3456 blocks for voxel grid
#define TMMB  (NVW*PIXB4)      // 2700 target-minmax blocks
#define DMMV  (NPIX/(256*2))   // 600 depth-minmax blocks per view (2 px/thread)
#define NOUTB (NVW*PIXB)       // 10800 normal-output blocks

// ==== zero-canonical scratch: .bss zero == canonical empty; consumers   ====
// ==== restore what they consume (g_last by grid, g_dz by final, scalars ====
// ==== by loss; g_grid fully rewritten before every read).               ====
__device__ __align__(16) int                g_last[NCELL];   // idx+1, 0 = empty
__device__ float                            g_grid[NCELL];
// packed z-buffer: stores ~((zbits<<32)|idx); atomicMax == min over (z,idx); 0 = no hit
__device__ __align__(16) unsigned long long g_dz[NVW*NPIX];
__device__ unsigned int g_dminE[NVW], g_tminE[NVW];  // ~bits of min (atomicMax, 0-canonical)
__device__ unsigned int g_dmax[NVW],  g_tmax[NVW];   // bits of max (vals>=0, 0-canonical)
__device__ float        g_lsum[NVW];
__device__ int          g_vcnt[NVW];

// XLA:CPU dot (no FMA contraction, left-assoc, strict rn): ((p0*m0 + p1*m1) + p2*m2)
__device__ __forceinline__ float dotrow(const float* M, float px, float py, float pz) {
    return __fadd_rn(__fadd_rn(__fmul_rn(px, M[0]), __fmul_rn(py, M[1])),
                     __fmul_rn(pz, M[2]));
}
// u = rn( (f*x)/zs + c ), strict
__device__ __forceinline__ int proj_pix(float f, float c, float x, float zs) {
    return __float2int_rn(__fadd_rn(__fdiv_rn(__fmul_rn(f, x), zs), c));
}

__device__ __forceinline__ void load_view_consts(const float* __restrict__ vm,
                                                 const float* __restrict__ intr,
                                                 float* s_vm, float* s_in) {
    int t = threadIdx.x;
    if (t < NVW * 12) s_vm[t] = vm[(t / 12) * 16 + (t % 12)];   // rows 0..2 of 4x4
    if (t < NVW * 4) {
        int v = t >> 2, k = t & 3;
        int off = (k == 0) ? 0 : (k == 1) ? 5 : (k == 2) ? 2 : 6; // fx,fy,cx,cy
        s_in[t] = intr[v * 16 + off];
    }
    __syncthreads();
}

// ---- L1 fused: [0,projB) scatter ; [projB,..) target-image min/max/count --
__global__ void k_scatter_tmm(const int4* __restrict__ coords,
                              const float* __restrict__ tgt, int n, int projB) {
    if ((int)blockIdx.x < projB) {
        int i = blockIdx.x * blockDim.x + threadIdx.x;
        if (i >= n) return;
        int4 q = coords[i];                    // (.x=0, .y=c1, .z=c2, .w=c3)
        atomicMax(&g_last[(q.w * GD + q.z) * GD + q.y], i + 1);  // last-write-wins
        return;
    }
    int b = blockIdx.x - projB;
    int v = b / PIXB4;
    int p4 = (b % PIXB4) * blockDim.x + threadIdx.x;
    float4 dt = reinterpret_cast<const float4*>(tgt)[v * (NPIX/4) + p4];
    float mnt = fminf(fminf(dt.x, dt.y), fminf(dt.z, dt.w));
    float mxt = fmaxf(fmaxf(dt.x, dt.y), fmaxf(dt.z, dt.w));
    int cnt = (dt.x != 0.f) + (dt.y != 0.f) + (dt.z != 0.f) + (dt.w != 0.f);
    for (int o = 16; o; o >>= 1) {
        mnt = fminf(mnt, __shfl_down_sync(0xffffffffu, mnt, o));
        mxt = fmaxf(mxt, __shfl_down_sync(0xffffffffu, mxt, o));
        cnt += __shfl_down_sync(0xffffffffu, cnt, o);
    }
    __shared__ float smnt[8], smxt[8];
    __shared__ int sc[8];
    int wid = threadIdx.x >> 5, lid = threadIdx.x & 31;
    if (lid == 0) { smnt[wid] = mnt; smxt[wid] = mxt; sc[wid] = cnt; }
    __syncthreads();
    if (threadIdx.x == 0) {
        for (int w = 1; w < 8; w++) {
            mnt = fminf(mnt, smnt[w]); mxt = fmaxf(mxt, smxt[w]); cnt += sc[w];
        }
        atomicMax(&g_tminE[v], ~__float_as_uint(mnt));   // encoded min (0-canonical)
        atomicMax(&g_tmax[v],   __float_as_uint(mxt));
        atomicAdd(&g_vcnt[v], cnt);
    }
}

// -- L2 fused: [0,GRIDB) grid materialize+clean ; [GRIDB,..) project (u64) --
__global__ void k_grid_project(const int4* __restrict__ coords,
                               const float* __restrict__ origin,
                               const float* __restrict__ vm,
                               const float* __restrict__ intr,
                               const float* __restrict__ sdf, int n) {
    if (blockIdx.x < GRIDB) {
        int c = blockIdx.x * blockDim.x + threadIdx.x;
        int idx = g_last[c];
        g_grid[c] = (idx > 0) ? __ldg(&sdf[idx - 1]) : 0.f;
        if (idx > 0) g_last[c] = 0;                     // self-clean (skip if clean)
        return;
    }
    __shared__ float s_vm[NVW * 12];
    __shared__ float s_in[NVW * 4];
    load_view_consts(vm, intr, s_vm, s_in);
    int i = (blockIdx.x - GRIDB) * blockDim.x + threadIdx.x;
    if (i >= n) return;
    int4 q = coords[i];
    float px = __fadd_rn((float)q.w, __ldg(&origin[0]));
    float py = __fadd_rn((float)q.z, __ldg(&origin[1]));
    float pz = __fadd_rn((float)q.y, __ldg(&origin[2]));
    #pragma unroll
    for (int v = 0; v < NVW; v++) {
        const float* M = &s_vm[v * 12];
        float x = __fadd_rn(dotrow(M,     px, py, pz), M[3]);
        float y = __fadd_rn(dotrow(M + 4, px, py, pz), M[7]);
        float z = __fadd_rn(dotrow(M + 8, px, py, pz), M[11]);
        float zs = (fabsf(z) < 1e-6f) ? 1e-6f : z;
        int u = proj_pix(s_in[v*4+0], s_in[v*4+2], x, zs);
        int w = proj_pix(s_in[v*4+1], s_in[v*4+3], y, zs);
        if (z > 0.025f && z < 100.0f && u >= 0 && u < WSZ && w >= 0 && w < HSZ) {
            unsigned long long packed =
                ((unsigned long long)__float_as_uint(z) << 32) | (unsigned)i;
            atomicMax(&g_dz[v * NPIX + w * WSZ + u], ~packed);  // == min (z, idx)
        }
    }
}

// -- L3 fused: [0,NOUTB) per-pixel normal output ; [NOUTB,..) depth minmax --
// (normal output depends only on z-buffer + grid + vm, NOT on dmm results)
__global__ void k_nout_dmm(const int4* __restrict__ coords,
                           const float* __restrict__ vm,
                           float* __restrict__ out) {
    if (blockIdx.x < NOUTB) {
        int v = blockIdx.x / PIXB;
        __shared__ float s_M[12];
        if (threadIdx.x < 12) s_M[threadIdx.x] = vm[v * 16 + threadIdx.x];  // rows 0..2
        __syncthreads();
        int p = (blockIdx.x % PIXB) * blockDim.x + threadIdx.x;
        int gp = v * NPIX + p;
        unsigned long long raw = g_dz[gp];
        float* nout = &out[1 + 2 * NVW * NPIX + 3 * gp];
        if (raw != 0ull) {
            unsigned idx = (unsigned)(~raw & 0xffffffffu);
            int4 q = coords[idx];                        // winning point
            float na = 0.f, nb = 0.f, nc = 0.f;          // central-diff normal
            if (q.w >= 1 && q.w <= GD-2 && q.z >= 1 && q.z <= GD-2 &&
                q.y >= 1 && q.y <= GD-2) {
                int base = (q.w * GD + q.z) * GD + q.y;
                na = __fsub_rn(g_grid[base + 1],     g_grid[base - 1]);
                nb = __fsub_rn(g_grid[base + GD],    g_grid[base - GD]);
                nc = __fsub_rn(g_grid[base + GD*GD], g_grid[base - GD*GD]);
            }
            float rx = dotrow(s_M,     na, nb, nc);
            float ry = dotrow(s_M + 4, na, nb, nc);
            float rz = dotrow(s_M + 8, na, nb, nc);
            float ss = __fadd_rn(__fadd_rn(__fmul_rn(rx, rx), __fmul_rn(ry, ry)),
                                 __fmul_rn(rz, rz));
            float len = fmaxf(__fsqrt_rn(ss), 1e-5f);
            __stcs(nout + 0, __fdiv_rn(-rx, len));
            __stcs(nout + 1, __fdiv_rn(-ry, len));
            __stcs(nout + 2, __fdiv_rn(-rz, len));
        } else {
            __stcs(nout + 0, 0.f);
            __stcs(nout + 1, 0.f);
            __stcs(nout + 2, 0.f);
        }
        return;
    }
    // ---- depth-image min/max (2 px/thread) ----
    int b = blockIdx.x - NOUTB;
    int v = b / DMMV;
    int p2 = (b % DMMV) * blockDim.x + threadIdx.x;
    ulonglong2 raw = reinterpret_cast<const ulonglong2*>(g_dz)[v * (NPIX/2) + p2];
    float d0 = raw.x ? __fmul_rn(__uint_as_float((unsigned)(~raw.x >> 32)), 0.04f) : 0.f;
    float d1 = raw.y ? __fmul_rn(__uint_as_float((unsigned)(~raw.y >> 32)), 0.04f) : 0.f;
    float mnd = fminf(d0, d1);
    float mxd = fmaxf(d0, d1);
    for (int o = 16; o; o >>= 1) {
        mnd = fminf(mnd, __shfl_down_sync(0xffffffffu, mnd, o));
        mxd = fmaxf(mxd, __shfl_down_sync(0xffffffffu, mxd, o));
    }
    __shared__ float smnd[8], smxd[8];
    int wid = threadIdx.x >> 5, lid = threadIdx.x & 31;
    if (lid == 0) { smnd[wid] = mnd; smxd[wid] = mxd; }
    __syncthreads();
    if (threadIdx.x == 0) {
        for (int w = 1; w < 8; w++) { mnd = fminf(mnd, smnd[w]); mxd = fmaxf(mxd, smxd[w]); }
        atomicMax(&g_dminE[v], ~__float_as_uint(mnd));
        atomicMax(&g_dmax[v],   __float_as_uint(mxd));
    }
}

// --- L4: depth/tgt normalize (2 px/thread) + loss + g_dz self-clean --------
__global__ void k_final(const float* __restrict__ tgt, float* __restrict__ out) {
    int v = blockIdx.y;
    int p2 = blockIdx.x * blockDim.x + threadIdx.x;      // 0..NPIX/2
    int gp2 = v * (NPIX/2) + p2;
    ulonglong2 raw = reinterpret_cast<const ulonglong2*>(g_dz)[gp2];
    float2 dt2 = reinterpret_cast<const float2*>(tgt)[gp2];
    float dmn = __uint_as_float(~g_dminE[v]);
    float drg = __fsub_rn(__uint_as_float(g_dmax[v]), dmn);
    float tmn = __uint_as_float(~g_tminE[v]);
    float trg = __fsub_rn(__uint_as_float(g_tmax[v]), tmn);
    int gp = 2 * gp2;

    float d0 = raw.x ? __fmul_rn(__uint_as_float((unsigned)(~raw.x >> 32)), 0.04f) : 0.f;
    float d1 = raw.y ? __fmul_rn(__uint_as_float((unsigned)(~raw.y >> 32)), 0.04f) : 0.f;
    float sd0 = __fsub_rn(d0, dmn), sd1 = __fsub_rn(d1, dmn);
    float dn0 = (drg != 0.f) ? __fdiv_rn(sd0, drg) : sd0;
    float dn1 = (drg != 0.f) ? __fdiv_rn(sd1, drg) : sd1;
    float st0 = __fsub_rn(dt2.x, tmn), st1 = __fsub_rn(dt2.y, tmn);
    float tn0 = (trg != 0.f) ? __fdiv_rn(st0, trg) : st0;
    float tn1 = (trg != 0.f) ? __fdiv_rn(st1, trg) : st1;
    __stcs(&out[1 + gp + 0], dn0);
    __stcs(&out[1 + gp + 1], dn1);
    __stcs(&out[1 + NVW * NPIX + gp + 0], tn0);
    __stcs(&out[1 + NVW * NPIX + gp + 1], tn1);
    if (raw.x | raw.y)
        reinterpret_cast<ulonglong2*>(g_dz)[gp2] = make_ulonglong2(0ull, 0ull); // clean
    float l = 0.f;
    if (dt2.x != 0.f) l += fabsf(__fsub_rn(dn0, tn0));
    if (dt2.y != 0.f) l += fabsf(__fsub_rn(dn1, tn1));
    for (int o = 16; o; o >>= 1) l += __shfl_down_sync(0xffffffffu, l, o);
    __shared__ float sl[8];
    int wid = threadIdx.x >> 5, lid = threadIdx.x & 31;
    if (lid == 0) sl[wid] = l;
    __syncthreads();
    if (threadIdx.x == 0) {
        for (int w = 1; w < 8; w++) l += sl[w];
        atomicAdd(&g_lsum[v], l);
    }
}

// ---------------- L5: loss + scalar self-clean ------------------------------
__global__ void k_loss(float* __restrict__ out) {
    if (threadIdx.x == 0) {
        float tot = 0.f;
        for (int v = 0; v < NVW; v++) {
            float c = (float)g_vcnt[v];
            float l = (g_vcnt[v] > 0) ? __fdiv_rn(g_lsum[v], fmaxf(c, 1.f)) : 0.f;
            tot = __fadd_rn(tot, __fdiv_rn(l, 9.0f));   // * WEIGHT(1) / N_VIEWS
            g_lsum[v] = 0.f; g_vcnt[v] = 0;             // self-clean
            g_dminE[v] = 0u; g_tminE[v] = 0u;
            g_dmax[v] = 0u;  g_tmax[v] = 0u;
        }
        out[0] = tot;
    }
}

// ---------------------------------------------------------------------------
extern "C" void kernel_launch(void* const* d_in, const int* in_sizes, int n_in,
                              void* d_out, int out_size) {
    const int4*  coords = (const int4*) d_in[0];
    const float* origin = (const float*)d_in[1];
    const float* sdf    = (const float*)d_in[2];
    // d_in[3] = sdf_target (unused by forward)
    const float* tgt    = (const float*)d_in[4];
    const float* intr   = (const float*)d_in[5];
    const float* vm     = (const float*)d_in[6];
    float* out = (float*)d_out;

    int n = in_sizes[0] / 4;
    if (n > MAXN) n = MAXN;
    const int tb = 256;
    int projB = (n + tb - 1) / tb;

    k_scatter_tmm<<<projB + TMMB, tb>>>(coords, tgt, n, projB);
    k_grid_project<<<GRIDB + projB, tb>>>(coords, origin, vm, intr, sdf, n);
    k_nout_dmm<<<NOUTB + NVW * DMMV, tb>>>(coords, vm, out);
    dim3 rg(PIXB2, NVW);
    k_final<<<rg, tb>>>(tgt, out);
    k_loss<<<1, 32>>>(out);
}

// round 14
// speedup vs baseline: 1.5122x; 1.0241x over previous
#include <cuda_runtime.h>

#define NVW   9
#define HSZ   480
#define WSZ   640
#define NPIX  (HSZ*WSZ)
#define GD    96
#define NCELL (GD*GD*GD)
#define MAXN  400000
#define PIXB4 (NPIX/(256*4))   // 300 blocks per view image (4 px/thread)
#define PIXB  (NPIX/256)       // 1200 blocks per view image (1 px/thread)
#define PIXB2 (NPIX/(256*2))   // 600 blocks per view image (2 px/thread)
#define GRIDB (NCELL/256)      // 3456 blocks for voxel grid
#define TMMB  (NVW*PIXB4)      // 2700 target-minmax blocks
#define DMMV  (NPIX/(256*2))   // 600 depth-minmax blocks per view (2 px/thread)
#define NOUTB (NVW*PIXB)       // 10800 normal-output blocks

// ==== zero-canonical scratch: .bss zero == canonical empty; consumers   ====
// ==== restore what they consume (g_last by grid, g_dz by final, scalars ====
// ==== by loss; g_grid fully rewritten before every read).               ====
__device__ __align__(16) int                g_last[NCELL];   // idx+1, 0 = empty
__device__ float                            g_grid[NCELL];
// packed z-buffer: stores ~((zbits<<32)|idx); atomicMax == min over (z,idx); 0 = no hit
__device__ __align__(16) unsigned long long g_dz[NVW*NPIX];
__device__ unsigned int g_dminE[NVW], g_tminE[NVW];  // ~bits of min (atomicMax, 0-canonical)
__device__ unsigned int g_dmax[NVW],  g_tmax[NVW];   // bits of max (vals>=0, 0-canonical)
__device__ float        g_lsum[NVW];
__device__ int          g_vcnt[NVW];

// XLA:CPU dot (no FMA contraction, left-assoc, strict rn): ((p0*m0 + p1*m1) + p2*m2)
__device__ __forceinline__ float dotrow(const float* M, float px, float py, float pz) {
    return __fadd_rn(__fadd_rn(__fmul_rn(px, M[0]), __fmul_rn(py, M[1])),
                     __fmul_rn(pz, M[2]));
}
// u = rn( (f*x)/zs + c ), strict
__device__ __forceinline__ int proj_pix(float f, float c, float x, float zs) {
    return __float2int_rn(__fadd_rn(__fdiv_rn(__fmul_rn(f, x), zs), c));
}

__device__ __forceinline__ void load_view_consts(const float* __restrict__ vm,
                                                 const float* __restrict__ intr,
                                                 float* s_vm, float* s_in) {
    int t = threadIdx.x;
    if (t < NVW * 12) s_vm[t] = vm[(t / 12) * 16 + (t % 12)];   // rows 0..2 of 4x4
    if (t < NVW * 4) {
        int v = t >> 2, k = t & 3;
        int off = (k == 0) ? 0 : (k == 1) ? 5 : (k == 2) ? 2 : 6; // fx,fy,cx,cy
        s_in[t] = intr[v * 16 + off];
    }
    __syncthreads();
}

// -- L1 fused: [0,projB) scatter+project (one point pass) ; [projB,..) tmm --
// (projection depends only on coords/origin/vm/intr, so it runs alongside
//  the g_last scatter instead of serialized behind it)
__global__ void k_point_tmm(const int4* __restrict__ coords,
                            const float* __restrict__ origin,
                            const float* __restrict__ vm,
                            const float* __restrict__ intr,
                            const float* __restrict__ tgt, int n, int projB) {
    if ((int)blockIdx.x < projB) {
        __shared__ float s_vm[NVW * 12];
        __shared__ float s_in[NVW * 4];
        load_view_consts(vm, intr, s_vm, s_in);
        int i = blockIdx.x * blockDim.x + threadIdx.x;
        if (i >= n) return;
        int4 q = coords[i];                    // (.x=0, .y=c1, .z=c2, .w=c3)
        atomicMax(&g_last[(q.w * GD + q.z) * GD + q.y], i + 1);  // last-write-wins
        float px = __fadd_rn((float)q.w, __ldg(&origin[0]));
        float py = __fadd_rn((float)q.z, __ldg(&origin[1]));
        float pz = __fadd_rn((float)q.y, __ldg(&origin[2]));
        #pragma unroll
        for (int v = 0; v < NVW; v++) {
            const float* M = &s_vm[v * 12];
            float x = __fadd_rn(dotrow(M,     px, py, pz), M[3]);
            float y = __fadd_rn(dotrow(M + 4, px, py, pz), M[7]);
            float z = __fadd_rn(dotrow(M + 8, px, py, pz), M[11]);
            float zs = (fabsf(z) < 1e-6f) ? 1e-6f : z;
            int u = proj_pix(s_in[v*4+0], s_in[v*4+2], x, zs);
            int w = proj_pix(s_in[v*4+1], s_in[v*4+3], y, zs);
            if (z > 0.025f && z < 100.0f && u >= 0 && u < WSZ && w >= 0 && w < HSZ) {
                unsigned long long packed =
                    ((unsigned long long)__float_as_uint(z) << 32) | (unsigned)i;
                atomicMax(&g_dz[v * NPIX + w * WSZ + u], ~packed);  // == min (z, idx)
            }
        }
        return;
    }
    // ---- target-image min/max/count (float4-vectorized) ----
    int b = blockIdx.x - projB;
    int v = b / PIXB4;
    int p4 = (b % PIXB4) * blockDim.x + threadIdx.x;
    float4 dt = reinterpret_cast<const float4*>(tgt)[v * (NPIX/4) + p4];
    float mnt = fminf(fminf(dt.x, dt.y), fminf(dt.z, dt.w));
    float mxt = fmaxf(fmaxf(dt.x, dt.y), fmaxf(dt.z, dt.w));
    int cnt = (dt.x != 0.f) + (dt.y != 0.f) + (dt.z != 0.f) + (dt.w != 0.f);
    for (int o = 16; o; o >>= 1) {
        mnt = fminf(mnt, __shfl_down_sync(0xffffffffu, mnt, o));
        mxt = fmaxf(mxt, __shfl_down_sync(0xffffffffu, mxt, o));
        cnt += __shfl_down_sync(0xffffffffu, cnt, o);
    }
    __shared__ float smnt[8], smxt[8];
    __shared__ int sc[8];
    int wid = threadIdx.x >> 5, lid = threadIdx.x & 31;
    if (lid == 0) { smnt[wid] = mnt; smxt[wid] = mxt; sc[wid] = cnt; }
    __syncthreads();
    if (threadIdx.x == 0) {
        for (int w = 1; w < 8; w++) {
            mnt = fminf(mnt, smnt[w]); mxt = fmaxf(mxt, smxt[w]); cnt += sc[w];
        }
        atomicMax(&g_tminE[v], ~__float_as_uint(mnt));   // encoded min (0-canonical)
        atomicMax(&g_tmax[v],   __float_as_uint(mxt));
        atomicAdd(&g_vcnt[v], cnt);
    }
}

// ---------------- L2: grid materialize + g_last self-clean ------------------
__global__ void k_grid(const float* __restrict__ sdf) {
    int c = blockIdx.x * blockDim.x + threadIdx.x;
    int idx = g_last[c];
    g_grid[c] = (idx > 0) ? __ldg(&sdf[idx - 1]) : 0.f;
    if (idx > 0) g_last[c] = 0;                         // self-clean (skip if clean)
}

// -- L3 fused: [0,NOUTB) per-pixel normal output ; [NOUTB,..) depth minmax --
// (normal output depends only on z-buffer + grid + vm, NOT on dmm results)
__global__ void k_nout_dmm(const int4* __restrict__ coords,
                           const float* __restrict__ vm,
                           float* __restrict__ out) {
    if (blockIdx.x < NOUTB) {
        int v = blockIdx.x / PIXB;
        __shared__ float s_M[12];
        if (threadIdx.x < 12) s_M[threadIdx.x] = vm[v * 16 + threadIdx.x];  // rows 0..2
        __syncthreads();
        int p = (blockIdx.x % PIXB) * blockDim.x + threadIdx.x;
        int gp = v * NPIX + p;
        unsigned long long raw = g_dz[gp];
        float* nout = &out[1 + 2 * NVW * NPIX + 3 * gp];
        if (raw != 0ull) {
            unsigned idx = (unsigned)(~raw & 0xffffffffu);
            int4 q = coords[idx];                        // winning point
            float na = 0.f, nb = 0.f, nc = 0.f;          // central-diff normal
            if (q.w >= 1 && q.w <= GD-2 && q.z >= 1 && q.z <= GD-2 &&
                q.y >= 1 && q.y <= GD-2) {
                int base = (q.w * GD + q.z) * GD + q.y;
                na = __fsub_rn(g_grid[base + 1],     g_grid[base - 1]);
                nb = __fsub_rn(g_grid[base + GD],    g_grid[base - GD]);
                nc = __fsub_rn(g_grid[base + GD*GD], g_grid[base - GD*GD]);
            }
            float rx = dotrow(s_M,     na, nb, nc);
            float ry = dotrow(s_M + 4, na, nb, nc);
            float rz = dotrow(s_M + 8, na, nb, nc);
            float ss = __fadd_rn(__fadd_rn(__fmul_rn(rx, rx), __fmul_rn(ry, ry)),
                                 __fmul_rn(rz, rz));
            float len = fmaxf(__fsqrt_rn(ss), 1e-5f);
            __stcs(nout + 0, __fdiv_rn(-rx, len));
            __stcs(nout + 1, __fdiv_rn(-ry, len));
            __stcs(nout + 2, __fdiv_rn(-rz, len));
        } else {
            __stcs(nout + 0, 0.f);
            __stcs(nout + 1, 0.f);
            __stcs(nout + 2, 0.f);
        }
        return;
    }
    // ---- depth-image min/max (2 px/thread) ----
    int b = blockIdx.x - NOUTB;
    int v = b / DMMV;
    int p2 = (b % DMMV) * blockDim.x + threadIdx.x;
    ulonglong2 raw = reinterpret_cast<const ulonglong2*>(g_dz)[v * (NPIX/2) + p2];
    float d0 = raw.x ? __fmul_rn(__uint_as_float((unsigned)(~raw.x >> 32)), 0.04f) : 0.f;
    float d1 = raw.y ? __fmul_rn(__uint_as_float((unsigned)(~raw.y >> 32)), 0.04f) : 0.f;
    float mnd = fminf(d0, d1);
    float mxd = fmaxf(d0, d1);
    for (int o = 16; o; o >>= 1) {
        mnd = fminf(mnd, __shfl_down_sync(0xffffffffu, mnd, o));
        mxd = fmaxf(mxd, __shfl_down_sync(0xffffffffu, mxd, o));
    }
    __shared__ float smnd[8], smxd[8];
    int wid = threadIdx.x >> 5, lid = threadIdx.x & 31;
    if (lid == 0) { smnd[wid] = mnd; smxd[wid] = mxd; }
    __syncthreads();
    if (threadIdx.x == 0) {
        for (int w = 1; w < 8; w++) { mnd = fminf(mnd, smnd[w]); mxd = fmaxf(mxd, smxd[w]); }
        atomicMax(&g_dminE[v], ~__float_as_uint(mnd));
        atomicMax(&g_dmax[v],   __float_as_uint(mxd));
    }
}

// --- L4: depth/tgt normalize (2 px/thread) + loss + g_dz self-clean --------
__global__ void k_final(const float* __restrict__ tgt, float* __restrict__ out) {
    int v = blockIdx.y;
    int p2 = blockIdx.x * blockDim.x + threadIdx.x;      // 0..NPIX/2
    int gp2 = v * (NPIX/2) + p2;
    ulonglong2 raw = reinterpret_cast<const ulonglong2*>(g_dz)[gp2];
    float2 dt2 = reinterpret_cast<const float2*>(tgt)[gp2];
    float dmn = __uint_as_float(~g_dminE[v]);
    float drg = __fsub_rn(__uint_as_float(g_dmax[v]), dmn);
    float tmn = __uint_as_float(~g_tminE[v]);
    float trg = __fsub_rn(__uint_as_float(g_tmax[v]), tmn);
    int gp = 2 * gp2;

    float d0 = raw.x ? __fmul_rn(__uint_as_float((unsigned)(~raw.x >> 32)), 0.04f) : 0.f;
    float d1 = raw.y ? __fmul_rn(__uint_as_float((unsigned)(~raw.y >> 32)), 0.04f) : 0.f;
    float sd0 = __fsub_rn(d0, dmn), sd1 = __fsub_rn(d1, dmn);
    float dn0 = (drg != 0.f) ? __fdiv_rn(sd0, drg) : sd0;
    float dn1 = (drg != 0.f) ? __fdiv_rn(sd1, drg) : sd1;
    float st0 = __fsub_rn(dt2.x, tmn), st1 = __fsub_rn(dt2.y, tmn);
    float tn0 = (trg != 0.f) ? __fdiv_rn(st0, trg) : st0;
    float tn1 = (trg != 0.f) ? __fdiv_rn(st1, trg) : st1;
    __stcs(&out[1 + gp + 0], dn0);
    __stcs(&out[1 + gp + 1], dn1);
    __stcs(&out[1 + NVW * NPIX + gp + 0], tn0);
    __stcs(&out[1 + NVW * NPIX + gp + 1], tn1);
    if (raw.x | raw.y)
        reinterpret_cast<ulonglong2*>(g_dz)[gp2] = make_ulonglong2(0ull, 0ull); // clean
    float l = 0.f;
    if (dt2.x != 0.f) l += fabsf(__fsub_rn(dn0, tn0));
    if (dt2.y != 0.f) l += fabsf(__fsub_rn(dn1, tn1));
    for (int o = 16; o; o >>= 1) l += __shfl_down_sync(0xffffffffu, l, o);
    __shared__ float sl[8];
    int wid = threadIdx.x >> 5, lid = threadIdx.x & 31;
    if (lid == 0) sl[wid] = l;
    __syncthreads();
    if (threadIdx.x == 0) {
        for (int w = 1; w < 8; w++) l += sl[w];
        atomicAdd(&g_lsum[v], l);
    }
}

// ---------------- L5: loss + scalar self-clean ------------------------------
__global__ void k_loss(float* __restrict__ out) {
    if (threadIdx.x == 0) {
        float tot = 0.f;
        for (int v = 0; v < NVW; v++) {
            float c = (float)g_vcnt[v];
            float l = (g_vcnt[v] > 0) ? __fdiv_rn(g_lsum[v], fmaxf(c, 1.f)) : 0.f;
            tot = __fadd_rn(tot, __fdiv_rn(l, 9.0f));   // * WEIGHT(1) / N_VIEWS
            g_lsum[v] = 0.f; g_vcnt[v] = 0;             // self-clean
            g_dminE[v] = 0u; g_tminE[v] = 0u;
            g_dmax[v] = 0u;  g_tmax[v] = 0u;
        }
        out[0] = tot;
    }
}

// ---------------------------------------------------------------------------
extern "C" void kernel_launch(void* const* d_in, const int* in_sizes, int n_in,
                              void* d_out, int out_size) {
    const int4*  coords = (const int4*) d_in[0];
    const float* origin = (const float*)d_in[1];
    const float* sdf    = (const float*)d_in[2];
    // d_in[3] = sdf_target (unused by forward)
    const float* tgt    = (const float*)d_in[4];
    const float* intr   = (const float*)d_in[5];
    const float* vm     = (const float*)d_in[6];
    float* out = (float*)d_out;

    int n = in_sizes[0] / 4;
    if (n > MAXN) n = MAXN;
    const int tb = 256;
    int projB = (n + tb - 1) / tb;

    k_point_tmm<<<projB + TMMB, tb>>>(coords, origin, vm, intr, tgt, n, projB);
    k_grid<<<GRIDB, tb>>>(sdf);
    k_nout_dmm<<<NOUTB + NVW * DMMV, tb>>>(coords, vm, out);
    dim3 rg(PIXB2, NVW);
    k_final<<<rg, tb>>>(tgt, out);
    k_loss<<<1, 32>>>(out);
}

// round 15
// speedup vs baseline: 1.5995x; 1.0577x over previous
#include <cuda_runtime.h>

#define NVW   9
#define HSZ   480
#define WSZ   640
#define NPIX  (HSZ*WSZ)
#define GD    96
#define NCELL (GD*GD*GD)
#define MAXN  400000
#define PIXB4 (NPIX/(256*4))   // 300 blocks per view image (4 px/thread)
#define PIXB  (NPIX/256)       // 1200 blocks per view image (1 px/thread)
#define PIXB2 (NPIX/(256*2))   // 600 blocks per view image (2 px/thread)
#define GRIDB (NCELL/256)      // 3456 blocks for voxel grid
#define TMMB  (NVW*PIXB4)      // 2700 target-minmax blocks
#define DMMV  (NPIX/(256*2))   // 600 depth-minmax blocks per view (2 px/thread)
#define NOUTB (NVW*PIXB)       // 10800 normal-output blocks

// ==== zero-canonical scratch: .bss zero == canonical empty; consumers   ====
// ==== restore what they consume (g_last by grid, g_dz by final, scalars ====
// ==== by loss; g_grid fully rewritten before every read).               ====
__device__ __align__(16) int                g_last[NCELL];   // idx+1, 0 = empty
__device__ float                            g_grid[NCELL];
// packed z-buffer: ~((zbits<<32) | (c3<<14|c2<<7|c1)); atomicMax == min; 0 = no hit
__device__ __align__(16) unsigned long long g_dz[NVW*NPIX];
__device__ unsigned int g_dminE[NVW], g_tminE[NVW];  // ~bits of min (atomicMax, 0-canonical)
__device__ unsigned int g_dmax[NVW],  g_tmax[NVW];   // bits of max (vals>=0, 0-canonical)
__device__ float        g_lsum[NVW];
__device__ int          g_vcnt[NVW];

// XLA:CPU dot (no FMA contraction, left-assoc, strict rn): ((p0*m0 + p1*m1) + p2*m2)
__device__ __forceinline__ float dotrow(const float* M, float px, float py, float pz) {
    return __fadd_rn(__fadd_rn(__fmul_rn(px, M[0]), __fmul_rn(py, M[1])),
                     __fmul_rn(pz, M[2]));
}
// u = rn( (f*x)/zs + c ), strict
__device__ __forceinline__ int proj_pix(float f, float c, float x, float zs) {
    return __float2int_rn(__fadd_rn(__fdiv_rn(__fmul_rn(f, x), zs), c));
}

__device__ __forceinline__ void load_view_consts(const float* __restrict__ vm,
                                                 const float* __restrict__ intr,
                                                 float* s_vm, float* s_in) {
    int t = threadIdx.x;
    if (t < NVW * 12) s_vm[t] = vm[(t / 12) * 16 + (t % 12)];   // rows 0..2 of 4x4
    if (t < NVW * 4) {
        int v = t >> 2, k = t & 3;
        int off = (k == 0) ? 0 : (k == 1) ? 5 : (k == 2) ? 2 : 6; // fx,fy,cx,cy
        s_in[t] = intr[v * 16 + off];
    }
    __syncthreads();
}

// -- L1 fused: [0,projB) scatter+project (one point pass) ; [projB,..) tmm --
__global__ void k_point_tmm(const int4* __restrict__ coords,
                            const float* __restrict__ origin,
                            const float* __restrict__ vm,
                            const float* __restrict__ intr,
                            const float* __restrict__ tgt, int n, int projB) {
    if ((int)blockIdx.x < projB) {
        __shared__ float s_vm[NVW * 12];
        __shared__ float s_in[NVW * 4];
        load_view_consts(vm, intr, s_vm, s_in);
        int i = blockIdx.x * blockDim.x + threadIdx.x;
        if (i >= n) return;
        int4 q = coords[i];                    // (.x=0, .y=c1, .z=c2, .w=c3)
        atomicMax(&g_last[(q.w * GD + q.z) * GD + q.y], i + 1);  // last-write-wins
        float px = __fadd_rn((float)q.w, __ldg(&origin[0]));
        float py = __fadd_rn((float)q.z, __ldg(&origin[1]));
        float pz = __fadd_rn((float)q.y, __ldg(&origin[2]));
        unsigned cellbits = ((unsigned)q.w << 14) | ((unsigned)q.z << 7) | (unsigned)q.y;
        #pragma unroll
        for (int v = 0; v < NVW; v++) {
            const float* M = &s_vm[v * 12];
            float x = __fadd_rn(dotrow(M,     px, py, pz), M[3]);
            float y = __fadd_rn(dotrow(M + 4, px, py, pz), M[7]);
            float z = __fadd_rn(dotrow(M + 8, px, py, pz), M[11]);
            float zs = (fabsf(z) < 1e-6f) ? 1e-6f : z;
            int u = proj_pix(s_in[v*4+0], s_in[v*4+2], x, zs);
            int w = proj_pix(s_in[v*4+1], s_in[v*4+3], y, zs);
            if (z > 0.025f && z < 100.0f && u >= 0 && u < WSZ && w >= 0 && w < HSZ) {
                unsigned long long packed =
                    ((unsigned long long)__float_as_uint(z) << 32) | cellbits;
                atomicMax(&g_dz[v * NPIX + w * WSZ + u], ~packed);  // == min (z, cell)
            }
        }
        return;
    }
    // ---- target-image min/max/count (float4-vectorized) ----
    int b = blockIdx.x - projB;
    int v = b / PIXB4;
    int p4 = (b % PIXB4) * blockDim.x + threadIdx.x;
    float4 dt = reinterpret_cast<const float4*>(tgt)[v * (NPIX/4) + p4];
    float mnt = fminf(fminf(dt.x, dt.y), fminf(dt.z, dt.w));
    float mxt = fmaxf(fmaxf(dt.x, dt.y), fmaxf(dt.z, dt.w));
    int cnt = (dt.x != 0.f) + (dt.y != 0.f) + (dt.z != 0.f) + (dt.w != 0.f);
    for (int o = 16; o; o >>= 1) {
        mnt = fminf(mnt, __shfl_down_sync(0xffffffffu, mnt, o));
        mxt = fmaxf(mxt, __shfl_down_sync(0xffffffffu, mxt, o));
        cnt += __shfl_down_sync(0xffffffffu, cnt, o);
    }
    __shared__ float smnt[8], smxt[8];
    __shared__ int sc[8];
    int wid = threadIdx.x >> 5, lid = threadIdx.x & 31;
    if (lid == 0) { smnt[wid] = mnt; smxt[wid] = mxt; sc[wid] = cnt; }
    __syncthreads();
    if (threadIdx.x == 0) {
        for (int w = 1; w < 8; w++) {
            mnt = fminf(mnt, smnt[w]); mxt = fmaxf(mxt, smxt[w]); cnt += sc[w];
        }
        atomicMax(&g_tminE[v], ~__float_as_uint(mnt));   // encoded min (0-canonical)
        atomicMax(&g_tmax[v],   __float_as_uint(mxt));
        atomicAdd(&g_vcnt[v], cnt);
    }
}

// ---------------- L2: grid materialize + g_last self-clean ------------------
__global__ void k_grid(const float* __restrict__ sdf) {
    int c = blockIdx.x * blockDim.x + threadIdx.x;
    int idx = g_last[c];
    g_grid[c] = (idx > 0) ? __ldg(&sdf[idx - 1]) : 0.f;
    if (idx > 0) g_last[c] = 0;                         // self-clean (skip if clean)
}

// -- L3 fused: [0,NOUTB) per-pixel normal output ; [NOUTB,..) depth minmax --
// (winner cell decoded from z-buffer payload — no random coords gather)
__global__ void k_nout_dmm(const float* __restrict__ vm,
                           float* __restrict__ out) {
    if (blockIdx.x < NOUTB) {
        int v = blockIdx.x / PIXB;
        __shared__ float s_M[12];
        if (threadIdx.x < 12) s_M[threadIdx.x] = vm[v * 16 + threadIdx.x];  // rows 0..2
        __syncthreads();
        int p = (blockIdx.x % PIXB) * blockDim.x + threadIdx.x;
        int gp = v * NPIX + p;
        unsigned long long raw = g_dz[gp];
        float* nout = &out[1 + 2 * NVW * NPIX + 3 * gp];
        if (raw != 0ull) {
            unsigned lo = (unsigned)(~raw & 0xffffffffu);
            int c1 = lo & 0x7f, c2 = (lo >> 7) & 0x7f, c3 = (lo >> 14) & 0x7f;
            float na = 0.f, nb = 0.f, nc = 0.f;          // central-diff normal
            if (c3 >= 1 && c3 <= GD-2 && c2 >= 1 && c2 <= GD-2 &&
                c1 >= 1 && c1 <= GD-2) {
                int base = (c3 * GD + c2) * GD + c1;
                na = __fsub_rn(g_grid[base + 1],     g_grid[base - 1]);
                nb = __fsub_rn(g_grid[base + GD],    g_grid[base - GD]);
                nc = __fsub_rn(g_grid[base + GD*GD], g_grid[base - GD*GD]);
            }
            float rx = dotrow(s_M,     na, nb, nc);
            float ry = dotrow(s_M + 4, na, nb, nc);
            float rz = dotrow(s_M + 8, na, nb, nc);
            float ss = __fadd_rn(__fadd_rn(__fmul_rn(rx, rx), __fmul_rn(ry, ry)),
                                 __fmul_rn(rz, rz));
            float len = fmaxf(__fsqrt_rn(ss), 1e-5f);
            __stcs(nout + 0, __fdiv_rn(-rx, len));
            __stcs(nout + 1, __fdiv_rn(-ry, len));
            __stcs(nout + 2, __fdiv_rn(-rz, len));
        } else {
            __stcs(nout + 0, 0.f);
            __stcs(nout + 1, 0.f);
            __stcs(nout + 2, 0.f);
        }
        return;
    }
    // ---- depth-image min/max (2 px/thread) ----
    int b = blockIdx.x - NOUTB;
    int v = b / DMMV;
    int p2 = (b % DMMV) * blockDim.x + threadIdx.x;
    ulonglong2 raw = reinterpret_cast<const ulonglong2*>(g_dz)[v * (NPIX/2) + p2];
    float d0 = raw.x ? __fmul_rn(__uint_as_float((unsigned)(~raw.x >> 32)), 0.04f) : 0.f;
    float d1 = raw.y ? __fmul_rn(__uint_as_float((unsigned)(~raw.y >> 32)), 0.04f) : 0.f;
    float mnd = fminf(d0, d1);
    float mxd = fmaxf(d0, d1);
    for (int o = 16; o; o >>= 1) {
        mnd = fminf(mnd, __shfl_down_sync(0xffffffffu, mnd, o));
        mxd = fmaxf(mxd, __shfl_down_sync(0xffffffffu, mxd, o));
    }
    __shared__ float smnd[8], smxd[8];
    int wid = threadIdx.x >> 5, lid = threadIdx.x & 31;
    if (lid == 0) { smnd[wid] = mnd; smxd[wid] = mxd; }
    __syncthreads();
    if (threadIdx.x == 0) {
        for (int w = 1; w < 8; w++) { mnd = fminf(mnd, smnd[w]); mxd = fmaxf(mxd, smxd[w]); }
        atomicMax(&g_dminE[v], ~__float_as_uint(mnd));
        atomicMax(&g_dmax[v],   __float_as_uint(mxd));
    }
}

// --- L4: depth/tgt normalize (2 px/thread) + loss + g_dz self-clean --------
__global__ void k_final(const float* __restrict__ tgt, float* __restrict__ out) {
    int v = blockIdx.y;
    int p2 = blockIdx.x * blockDim.x + threadIdx.x;      // 0..NPIX/2
    int gp2 = v * (NPIX/2) + p2;
    ulonglong2 raw = reinterpret_cast<const ulonglong2*>(g_dz)[gp2];
    float2 dt2 = reinterpret_cast<const float2*>(tgt)[gp2];
    float dmn = __uint_as_float(~g_dminE[v]);
    float drg = __fsub_rn(__uint_as_float(g_dmax[v]), dmn);
    float tmn = __uint_as_float(~g_tminE[v]);
    float trg = __fsub_rn(__uint_as_float(g_tmax[v]), tmn);
    int gp = 2 * gp2;

    float d0 = raw.x ? __fmul_rn(__uint_as_float((unsigned)(~raw.x >> 32)), 0.04f) : 0.f;
    float d1 = raw.y ? __fmul_rn(__uint_as_float((unsigned)(~raw.y >> 32)), 0.04f) : 0.f;
    float sd0 = __fsub_rn(d0, dmn), sd1 = __fsub_rn(d1, dmn);
    float dn0 = (drg != 0.f) ? __fdiv_rn(sd0, drg) : sd0;
    float dn1 = (drg != 0.f) ? __fdiv_rn(sd1, drg) : sd1;
    float st0 = __fsub_rn(dt2.x, tmn), st1 = __fsub_rn(dt2.y, tmn);
    float tn0 = (trg != 0.f) ? __fdiv_rn(st0, trg) : st0;
    float tn1 = (trg != 0.f) ? __fdiv_rn(st1, trg) : st1;
    __stcs(&out[1 + gp + 0], dn0);
    __stcs(&out[1 + gp + 1], dn1);
    __stcs(&out[1 + NVW * NPIX + gp + 0], tn0);
    __stcs(&out[1 + NVW * NPIX + gp + 1], tn1);
    if (raw.x | raw.y)
        reinterpret_cast<ulonglong2*>(g_dz)[gp2] = make_ulonglong2(0ull, 0ull); // clean
    float l = 0.f;
    if (dt2.x != 0.f) l += fabsf(__fsub_rn(dn0, tn0));
    if (dt2.y != 0.f) l += fabsf(__fsub_rn(dn1, tn1));
    for (int o = 16; o; o >>= 1) l += __shfl_down_sync(0xffffffffu, l, o);
    __shared__ float sl[8];
    int wid = threadIdx.x >> 5, lid = threadIdx.x & 31;
    if (lid == 0) sl[wid] = l;
    __syncthreads();
    if (threadIdx.x == 0) {
        for (int w = 1; w < 8; w++) l += sl[w];
        atomicAdd(&g_lsum[v], l);
    }
}

// ---------------- L5: loss + scalar self-clean ------------------------------
__global__ void k_loss(float* __restrict__ out) {
    if (threadIdx.x == 0) {
        float tot = 0.f;
        for (int v = 0; v < NVW; v++) {
            float c = (float)g_vcnt[v];
            float l = (g_vcnt[v] > 0) ? __fdiv_rn(g_lsum[v], fmaxf(c, 1.f)) : 0.f;
            tot = __fadd_rn(tot, __fdiv_rn(l, 9.0f));   // * WEIGHT(1) / N_VIEWS
            g_lsum[v] = 0.f; g_vcnt[v] = 0;             // self-clean
            g_dminE[v] = 0u; g_tminE[v] = 0u;
            g_dmax[v] = 0u;  g_tmax[v] = 0u;
        }
        out[0] = tot;
    }
}

// ---------------------------------------------------------------------------
extern "C" void kernel_launch(void* const* d_in, const int* in_sizes, int n_in,
                              void* d_out, int out_size) {
    const int4*  coords = (const int4*) d_in[0];
    const float* origin = (const float*)d_in[1];
    const float* sdf    = (const float*)d_in[2];
    // d_in[3] = sdf_target (unused by forward)
    const float* tgt    = (const float*)d_in[4];
    const float* intr   = (const float*)d_in[5];
    const float* vm     = (const float*)d_in[6];
    float* out = (float*)d_out;

    int n = in_sizes[0] / 4;
    if (n > MAXN) n = MAXN;
    const int tb = 256;
    int projB = (n + tb - 1) / tb;

    k_point_tmm<<<projB + TMMB, tb>>>(coords, origin, vm, intr, tgt, n, projB);
    k_grid<<<GRIDB, tb>>>(sdf);
    k_nout_dmm<<<NOUTB + NVW * DMMV, tb>>>(vm, out);
    dim3 rg(PIXB2, NVW);
    k_final<<<rg, tb>>>(tgt, out);
    k_loss<<<1, 32>>>(out);
}

// round 16
// speedup vs baseline: 1.6544x; 1.0343x over previous
#include <cuda_runtime.h>

#define NVW   9
#define HSZ   480
#define WSZ   640
#define NPIX  (HSZ*WSZ)
#define GD    96
#define NCELL (GD*GD*GD)
#define MAXN  400000
#define PIXB4 (NPIX/(256*4))   // 300 blocks per view image (4 px/thread)
#define PIXB  (NPIX/256)       // 1200 blocks per view image (1 px/thread)
#define GRIDB (NCELL/256)      // 3456 blocks for voxel grid
#define TMMB  (NVW*PIXB4)      // 2700 target-minmax blocks
#define DMMV  (NPIX/(256*2))   // 600 depth-minmax blocks per view (2 px/thread)

// ==== zero-canonical scratch: .bss zero == canonical empty; consumers   ====
// ==== restore what they consume (g_last by grid, g_dz by pixel pass,    ====
// ==== scalars by loss; g_grid fully rewritten before every read).       ====
__device__ __align__(16) int                g_last[NCELL];   // idx+1, 0 = empty
__device__ float                            g_grid[NCELL];
// packed z-buffer: ~((zbits<<32) | (c3<<14|c2<<7|c1)); atomicMax == min; 0 = no hit
__device__ __align__(16) unsigned long long g_dz[NVW*NPIX];
__device__ unsigned int g_dminE[NVW], g_tminE[NVW];  // ~bits of min (atomicMax, 0-canonical)
__device__ unsigned int g_dmax[NVW],  g_tmax[NVW];   // bits of max (vals>=0, 0-canonical)
__device__ float        g_lsum[NVW];
__device__ int          g_vcnt[NVW];

// XLA:CPU dot (no FMA contraction, left-assoc, strict rn): ((p0*m0 + p1*m1) + p2*m2)
__device__ __forceinline__ float dotrow(const float* M, float px, float py, float pz) {
    return __fadd_rn(__fadd_rn(__fmul_rn(px, M[0]), __fmul_rn(py, M[1])),
                     __fmul_rn(pz, M[2]));
}
// u = rn( (f*x)/zs + c ), strict
__device__ __forceinline__ int proj_pix(float f, float c, float x, float zs) {
    return __float2int_rn(__fadd_rn(__fdiv_rn(__fmul_rn(f, x), zs), c));
}

__device__ __forceinline__ void load_view_consts(const float* __restrict__ vm,
                                                 const float* __restrict__ intr,
                                                 float* s_vm, float* s_in) {
    int t = threadIdx.x;
    if (t < NVW * 12) s_vm[t] = vm[(t / 12) * 16 + (t % 12)];   // rows 0..2 of 4x4
    if (t < NVW * 4) {
        int v = t >> 2, k = t & 3;
        int off = (k == 0) ? 0 : (k == 1) ? 5 : (k == 2) ? 2 : 6; // fx,fy,cx,cy
        s_in[t] = intr[v * 16 + off];
    }
    __syncthreads();
}

// -- L1 fused: [0,projB) scatter+project (one point pass) ; [projB,..) tmm --
__global__ void k_point_tmm(const int4* __restrict__ coords,
                            const float* __restrict__ origin,
                            const float* __restrict__ vm,
                            const float* __restrict__ intr,
                            const float* __restrict__ tgt, int n, int projB) {
    if ((int)blockIdx.x < projB) {
        __shared__ float s_vm[NVW * 12];
        __shared__ float s_in[NVW * 4];
        load_view_consts(vm, intr, s_vm, s_in);
        int i = blockIdx.x * blockDim.x + threadIdx.x;
        if (i >= n) return;
        int4 q = coords[i];                    // (.x=0, .y=c1, .z=c2, .w=c3)
        atomicMax(&g_last[(q.w * GD + q.z) * GD + q.y], i + 1);  // last-write-wins
        float px = __fadd_rn((float)q.w, __ldg(&origin[0]));
        float py = __fadd_rn((float)q.z, __ldg(&origin[1]));
        float pz = __fadd_rn((float)q.y, __ldg(&origin[2]));
        unsigned cellbits = ((unsigned)q.w << 14) | ((unsigned)q.z << 7) | (unsigned)q.y;
        #pragma unroll
        for (int v = 0; v < NVW; v++) {
            const float* M = &s_vm[v * 12];
            float x = __fadd_rn(dotrow(M,     px, py, pz), M[3]);
            float y = __fadd_rn(dotrow(M + 4, px, py, pz), M[7]);
            float z = __fadd_rn(dotrow(M + 8, px, py, pz), M[11]);
            float zs = (fabsf(z) < 1e-6f) ? 1e-6f : z;
            int u = proj_pix(s_in[v*4+0], s_in[v*4+2], x, zs);
            int w = proj_pix(s_in[v*4+1], s_in[v*4+3], y, zs);
            if (z > 0.025f && z < 100.0f && u >= 0 && u < WSZ && w >= 0 && w < HSZ) {
                unsigned long long packed =
                    ((unsigned long long)__float_as_uint(z) << 32) | cellbits;
                atomicMax(&g_dz[v * NPIX + w * WSZ + u], ~packed);  // == min (z, cell)
            }
        }
        return;
    }
    // ---- target-image min/max/count (float4-vectorized) ----
    int b = blockIdx.x - projB;
    int v = b / PIXB4;
    int p4 = (b % PIXB4) * blockDim.x + threadIdx.x;
    float4 dt = reinterpret_cast<const float4*>(tgt)[v * (NPIX/4) + p4];
    float mnt = fminf(fminf(dt.x, dt.y), fminf(dt.z, dt.w));
    float mxt = fmaxf(fmaxf(dt.x, dt.y), fmaxf(dt.z, dt.w));
    int cnt = (dt.x != 0.f) + (dt.y != 0.f) + (dt.z != 0.f) + (dt.w != 0.f);
    for (int o = 16; o; o >>= 1) {
        mnt = fminf(mnt, __shfl_down_sync(0xffffffffu, mnt, o));
        mxt = fmaxf(mxt, __shfl_down_sync(0xffffffffu, mxt, o));
        cnt += __shfl_down_sync(0xffffffffu, cnt, o);
    }
    __shared__ float smnt[8], smxt[8];
    __shared__ int sc[8];
    int wid = threadIdx.x >> 5, lid = threadIdx.x & 31;
    if (lid == 0) { smnt[wid] = mnt; smxt[wid] = mxt; sc[wid] = cnt; }
    __syncthreads();
    if (threadIdx.x == 0) {
        for (int w = 1; w < 8; w++) {
            mnt = fminf(mnt, smnt[w]); mxt = fmaxf(mxt, smxt[w]); cnt += sc[w];
        }
        atomicMax(&g_tminE[v], ~__float_as_uint(mnt));   // encoded min (0-canonical)
        atomicMax(&g_tmax[v],   __float_as_uint(mxt));
        atomicAdd(&g_vcnt[v], cnt);
    }
}

// -- L2 fused: [0,GRIDB) grid materialize+clean ; [GRIDB,..) depth minmax ---
// (both depend only on L1's completed scatter / z-buffer)
__global__ void k_grid_dmm(const float* __restrict__ sdf) {
    if (blockIdx.x < GRIDB) {
        int c = blockIdx.x * blockDim.x + threadIdx.x;
        int idx = g_last[c];
        g_grid[c] = (idx > 0) ? __ldg(&sdf[idx - 1]) : 0.f;
        if (idx > 0) g_last[c] = 0;                     // self-clean (skip if clean)
        return;
    }
    int b = blockIdx.x - GRIDB;
    int v = b / DMMV;
    int p2 = (b % DMMV) * blockDim.x + threadIdx.x;
    ulonglong2 raw = reinterpret_cast<const ulonglong2*>(g_dz)[v * (NPIX/2) + p2];
    float d0 = raw.x ? __fmul_rn(__uint_as_float((unsigned)(~raw.x >> 32)), 0.04f) : 0.f;
    float d1 = raw.y ? __fmul_rn(__uint_as_float((unsigned)(~raw.y >> 32)), 0.04f) : 0.f;
    float mnd = fminf(d0, d1);
    float mxd = fmaxf(d0, d1);
    for (int o = 16; o; o >>= 1) {
        mnd = fminf(mnd, __shfl_down_sync(0xffffffffu, mnd, o));
        mxd = fmaxf(mxd, __shfl_down_sync(0xffffffffu, mxd, o));
    }
    __shared__ float smnd[8], smxd[8];
    int wid = threadIdx.x >> 5, lid = threadIdx.x & 31;
    if (lid == 0) { smnd[wid] = mnd; smxd[wid] = mxd; }
    __syncthreads();
    if (threadIdx.x == 0) {
        for (int w = 1; w < 8; w++) { mnd = fminf(mnd, smnd[w]); mxd = fmaxf(mxd, smxd[w]); }
        atomicMax(&g_dminE[v], ~__float_as_uint(mnd));
        atomicMax(&g_dmax[v],   __float_as_uint(mxd));
    }
}

// --- L3: single per-pixel pass — depth/tgt normalize + winner normal +
//         loss + g_dz self-clean (reads g_dz exactly once) ------------------
__global__ void k_pixel(const float* __restrict__ vm,
                        const float* __restrict__ tgt, float* __restrict__ out) {
    int v = blockIdx.y;
    __shared__ float s_M[12];
    if (threadIdx.x < 12) s_M[threadIdx.x] = vm[v * 16 + threadIdx.x];  // rows 0..2
    __syncthreads();
    int p = blockIdx.x * blockDim.x + threadIdx.x;
    int gp = v * NPIX + p;
    unsigned long long raw = g_dz[gp];
    bool hit = raw != 0ull;
    unsigned long long packed = ~raw;
    float dimg = hit ? __fmul_rn(__uint_as_float((unsigned)(packed >> 32)), 0.04f) : 0.f;
    float dmn = __uint_as_float(~g_dminE[v]);
    float sd  = __fsub_rn(dimg, dmn);
    float drg = __fsub_rn(__uint_as_float(g_dmax[v]), dmn);
    float dn = (drg != 0.f) ? __fdiv_rn(sd, drg) : sd;
    float dt = tgt[gp];
    float tmn = __uint_as_float(~g_tminE[v]);
    float st  = __fsub_rn(dt, tmn);
    float trg = __fsub_rn(__uint_as_float(g_tmax[v]), tmn);
    float tn = (trg != 0.f) ? __fdiv_rn(st, trg) : st;
    __stcs(&out[1 + gp], dn);                          // streaming: don't pollute L2
    __stcs(&out[1 + NVW * NPIX + gp], tn);
    float* nout = &out[1 + 2 * NVW * NPIX + 3 * gp];
    if (hit) {
        unsigned lo = (unsigned)(packed & 0xffffffffu);
        int c1 = lo & 0x7f, c2 = (lo >> 7) & 0x7f, c3 = (lo >> 14) & 0x7f;
        float na = 0.f, nb = 0.f, nc = 0.f;            // central-diff normal
        if (c3 >= 1 && c3 <= GD-2 && c2 >= 1 && c2 <= GD-2 && c1 >= 1 && c1 <= GD-2) {
            int base = (c3 * GD + c2) * GD + c1;
            na = __fsub_rn(g_grid[base + 1],     g_grid[base - 1]);
            nb = __fsub_rn(g_grid[base + GD],    g_grid[base - GD]);
            nc = __fsub_rn(g_grid[base + GD*GD], g_grid[base - GD*GD]);
        }
        float rx = dotrow(s_M,     na, nb, nc);
        float ry = dotrow(s_M + 4, na, nb, nc);
        float rz = dotrow(s_M + 8, na, nb, nc);
        float ss = __fadd_rn(__fadd_rn(__fmul_rn(rx, rx), __fmul_rn(ry, ry)),
                             __fmul_rn(rz, rz));
        float len = fmaxf(__fsqrt_rn(ss), 1e-5f);
        __stcs(nout + 0, __fdiv_rn(-rx, len));
        __stcs(nout + 1, __fdiv_rn(-ry, len));
        __stcs(nout + 2, __fdiv_rn(-rz, len));
        g_dz[gp] = 0ull;                               // self-clean
    } else {
        __stcs(nout + 0, 0.f);
        __stcs(nout + 1, 0.f);
        __stcs(nout + 2, 0.f);
    }
    float l = (dt != 0.f) ? fabsf(__fsub_rn(dn, tn)) : 0.f;
    for (int o = 16; o; o >>= 1) l += __shfl_down_sync(0xffffffffu, l, o);
    __shared__ float sl[8];
    int wid = threadIdx.x >> 5, lid = threadIdx.x & 31;
    if (lid == 0) sl[wid] = l;
    __syncthreads();
    if (threadIdx.x == 0) {
        for (int w = 1; w < 8; w++) l += sl[w];
        atomicAdd(&g_lsum[v], l);
    }
}

// ---------------- L4: loss + scalar self-clean ------------------------------
__global__ void k_loss(float* __restrict__ out) {
    if (threadIdx.x == 0) {
        float tot = 0.f;
        for (int v = 0; v < NVW; v++) {
            float c = (float)g_vcnt[v];
            float l = (g_vcnt[v] > 0) ? __fdiv_rn(g_lsum[v], fmaxf(c, 1.f)) : 0.f;
            tot = __fadd_rn(tot, __fdiv_rn(l, 9.0f));   // * WEIGHT(1) / N_VIEWS
            g_lsum[v] = 0.f; g_vcnt[v] = 0;             // self-clean
            g_dminE[v] = 0u; g_tminE[v] = 0u;
            g_dmax[v] = 0u;  g_tmax[v] = 0u;
        }
        out[0] = tot;
    }
}

// ---------------------------------------------------------------------------
extern "C" void kernel_launch(void* const* d_in, const int* in_sizes, int n_in,
                              void* d_out, int out_size) {
    const int4*  coords = (const int4*) d_in[0];
    const float* origin = (const float*)d_in[1];
    const float* sdf    = (const float*)d_in[2];
    // d_in[3] = sdf_target (unused by forward)
    const float* tgt    = (const float*)d_in[4];
    const float* intr   = (const float*)d_in[5];
    const float* vm     = (const float*)d_in[6];
    float* out = (float*)d_out;

    int n = in_sizes[0] / 4;
    if (n > MAXN) n = MAXN;
    const int tb = 256;
    int projB = (n + tb - 1) / tb;

    k_point_tmm<<<projB + TMMB, tb>>>(coords, origin, vm, intr, tgt, n, projB);
    k_grid_dmm<<<GRIDB + NVW * DMMV, tb>>>(sdf);
    dim3 rg(PIXB, NVW);
    k_pixel<<<rg, tb>>>(vm, tgt, out);
    k_loss<<<1, 32>>>(out);
}

// round 17
// speedup vs baseline: 1.6781x; 1.0143x over previous
#include <cuda_runtime.h>

#define NVW   9
#define HSZ   480
#define WSZ   640
#define NPIX  (HSZ*WSZ)
#define GD    96
#define NCELL (GD*GD*GD)
#define MAXN  400000
#define PIXB4 (NPIX/(256*4))   // 300 blocks per view image (4 px/thread)
#define PIXB  (NPIX/256)       // 1200 blocks per view image (1 px/thread)
#define GRIDB (NCELL/256)      // 3456 blocks for voxel grid
#define TMMB  (NVW*PIXB4)      // 2700 target-minmax blocks
#define DMMV  (NPIX/(256*2))   // 600 depth-minmax blocks per view (2 px/thread)

// ==== zero-canonical scratch: .bss zero == canonical empty; consumers   ====
// ==== restore what they consume (g_last by grid, g_dz by pixel pass,    ====
// ==== scalars by loss; g_grid fully rewritten before every read).       ====
__device__ __align__(16) int                g_last[NCELL];   // idx+1, 0 = empty
__device__ float                            g_grid[NCELL];
// packed z-buffer: ~((zbits<<32) | (c3<<14|c2<<7|c1)); atomicMax == min; 0 = no hit
__device__ __align__(16) unsigned long long g_dz[NVW*NPIX];
__device__ unsigned int g_dminE[NVW], g_tminE[NVW];  // ~bits of min (atomicMax, 0-canonical)
__device__ unsigned int g_dmax[NVW],  g_tmax[NVW];   // bits of max (vals>=0, 0-canonical)
__device__ float        g_lsum[NVW];
__device__ int          g_vcnt[NVW];

// XLA:CPU dot (no FMA contraction, left-assoc, strict rn): ((p0*m0 + p1*m1) + p2*m2)
__device__ __forceinline__ float dotrow(const float* M, float px, float py, float pz) {
    return __fadd_rn(__fadd_rn(__fmul_rn(px, M[0]), __fmul_rn(py, M[1])),
                     __fmul_rn(pz, M[2]));
}
// u = rn( (f*x)/zs + c ), strict
__device__ __forceinline__ int proj_pix(float f, float c, float x, float zs) {
    return __float2int_rn(__fadd_rn(__fdiv_rn(__fmul_rn(f, x), zs), c));
}

__device__ __forceinline__ void load_view_consts(const float* __restrict__ vm,
                                                 const float* __restrict__ intr,
                                                 float* s_vm, float* s_in) {
    int t = threadIdx.x;
    if (t < NVW * 12) s_vm[t] = vm[(t / 12) * 16 + (t % 12)];   // rows 0..2 of 4x4
    if (t < NVW * 4) {
        int v = t >> 2, k = t & 3;
        int off = (k == 0) ? 0 : (k == 1) ? 5 : (k == 2) ? 2 : 6; // fx,fy,cx,cy
        s_in[t] = intr[v * 16 + off];
    }
    __syncthreads();
}

// -- L1 fused: [0,projB) scatter+project (one point pass) ; [projB,..) tmm --
__global__ void k_point_tmm(const int4* __restrict__ coords,
                            const float* __restrict__ origin,
                            const float* __restrict__ vm,
                            const float* __restrict__ intr,
                            const float* __restrict__ tgt, int n, int projB) {
    if ((int)blockIdx.x < projB) {
        __shared__ float s_vm[NVW * 12];
        __shared__ float s_in[NVW * 4];
        load_view_consts(vm, intr, s_vm, s_in);
        int i = blockIdx.x * blockDim.x + threadIdx.x;
        if (i >= n) return;
        int4 q = coords[i];                    // (.x=0, .y=c1, .z=c2, .w=c3)
        atomicMax(&g_last[(q.w * GD + q.z) * GD + q.y], i + 1);  // last-write-wins
        float px = __fadd_rn((float)q.w, __ldg(&origin[0]));
        float py = __fadd_rn((float)q.z, __ldg(&origin[1]));
        float pz = __fadd_rn((float)q.y, __ldg(&origin[2]));
        unsigned cellbits = ((unsigned)q.w << 14) | ((unsigned)q.z << 7) | (unsigned)q.y;
        #pragma unroll
        for (int v = 0; v < NVW; v++) {
            const float* M = &s_vm[v * 12];
            float x = __fadd_rn(dotrow(M,     px, py, pz), M[3]);
            float y = __fadd_rn(dotrow(M + 4, px, py, pz), M[7]);
            float z = __fadd_rn(dotrow(M + 8, px, py, pz), M[11]);
            float zs = (fabsf(z) < 1e-6f) ? 1e-6f : z;
            int u = proj_pix(s_in[v*4+0], s_in[v*4+2], x, zs);
            int w = proj_pix(s_in[v*4+1], s_in[v*4+3], y, zs);
            if (z > 0.025f && z < 100.0f && u >= 0 && u < WSZ && w >= 0 && w < HSZ) {
                unsigned long long packed =
                    ((unsigned long long)__float_as_uint(z) << 32) | cellbits;
                atomicMax(&g_dz[v * NPIX + w * WSZ + u], ~packed);  // == min (z, cell)
            }
        }
        return;
    }
    // ---- target-image min/max/count (float4-vectorized) ----
    int b = blockIdx.x - projB;
    int v = b / PIXB4;
    int p4 = (b % PIXB4) * blockDim.x + threadIdx.x;
    float4 dt = reinterpret_cast<const float4*>(tgt)[v * (NPIX/4) + p4];
    float mnt = fminf(fminf(dt.x, dt.y), fminf(dt.z, dt.w));
    float mxt = fmaxf(fmaxf(dt.x, dt.y), fmaxf(dt.z, dt.w));
    int cnt = (dt.x != 0.f) + (dt.y != 0.f) + (dt.z != 0.f) + (dt.w != 0.f);
    for (int o = 16; o; o >>= 1) {
        mnt = fminf(mnt, __shfl_down_sync(0xffffffffu, mnt, o));
        mxt = fmaxf(mxt, __shfl_down_sync(0xffffffffu, mxt, o));
        cnt += __shfl_down_sync(0xffffffffu, cnt, o);
    }
    __shared__ float smnt[8], smxt[8];
    __shared__ int sc[8];
    int wid = threadIdx.x >> 5, lid = threadIdx.x & 31;
    if (lid == 0) { smnt[wid] = mnt; smxt[wid] = mxt; sc[wid] = cnt; }
    __syncthreads();
    if (threadIdx.x == 0) {
        for (int w = 1; w < 8; w++) {
            mnt = fminf(mnt, smnt[w]); mxt = fmaxf(mxt, smxt[w]); cnt += sc[w];
        }
        atomicMax(&g_tminE[v], ~__float_as_uint(mnt));   // encoded min (0-canonical)
        atomicMax(&g_tmax[v],   __float_as_uint(mxt));
        atomicAdd(&g_vcnt[v], cnt);
    }
}

// -- L2 fused: [0,GRIDB) grid materialize+clean ; [GRIDB,..) depth minmax ---
// (both depend only on L1's completed scatter / z-buffer)
__global__ void k_grid_dmm(const float* __restrict__ sdf) {
    if (blockIdx.x < GRIDB) {
        int c = blockIdx.x * blockDim.x + threadIdx.x;
        int idx = g_last[c];
        g_grid[c] = (idx > 0) ? __ldg(&sdf[idx - 1]) : 0.f;
        if (idx > 0) g_last[c] = 0;                     // self-clean (skip if clean)
        return;
    }
    int b = blockIdx.x - GRIDB;
    int v = b / DMMV;
    int p2 = (b % DMMV) * blockDim.x + threadIdx.x;
    ulonglong2 raw = reinterpret_cast<const ulonglong2*>(g_dz)[v * (NPIX/2) + p2];
    float d0 = raw.x ? __fmul_rn(__uint_as_float((unsigned)(~raw.x >> 32)), 0.04f) : 0.f;
    float d1 = raw.y ? __fmul_rn(__uint_as_float((unsigned)(~raw.y >> 32)), 0.04f) : 0.f;
    float mnd = fminf(d0, d1);
    float mxd = fmaxf(d0, d1);
    for (int o = 16; o; o >>= 1) {
        mnd = fminf(mnd, __shfl_down_sync(0xffffffffu, mnd, o));
        mxd = fmaxf(mxd, __shfl_down_sync(0xffffffffu, mxd, o));
    }
    __shared__ float smnd[8], smxd[8];
    int wid = threadIdx.x >> 5, lid = threadIdx.x & 31;
    if (lid == 0) { smnd[wid] = mnd; smxd[wid] = mxd; }
    __syncthreads();
    if (threadIdx.x == 0) {
        for (int w = 1; w < 8; w++) { mnd = fminf(mnd, smnd[w]); mxd = fmaxf(mxd, smxd[w]); }
        atomicMax(&g_dminE[v], ~__float_as_uint(mnd));
        atomicMax(&g_dmax[v],   __float_as_uint(mxd));
    }
}

// --- L3: single per-pixel pass — depth/tgt normalize + winner normal +
//         loss + g_dz self-clean (reads g_dz exactly once) ------------------
__global__ void k_pixel(const float* __restrict__ vm,
                        const float* __restrict__ tgt, float* __restrict__ out) {
    int v = blockIdx.y;
    __shared__ float s_M[12];
    if (threadIdx.x < 12) s_M[threadIdx.x] = vm[v * 16 + threadIdx.x];  // rows 0..2
    __syncthreads();
    int p = blockIdx.x * blockDim.x + threadIdx.x;
    int gp = v * NPIX + p;
    unsigned long long raw = g_dz[gp];
    bool hit = raw != 0ull;
    unsigned long long packed = ~raw;
    float dimg = hit ? __fmul_rn(__uint_as_float((unsigned)(packed >> 32)), 0.04f) : 0.f;
    float dmn = __uint_as_float(~g_dminE[v]);
    float sd  = __fsub_rn(dimg, dmn);
    float drg = __fsub_rn(__uint_as_float(g_dmax[v]), dmn);
    float dn = (drg != 0.f) ? __fdiv_rn(sd, drg) : sd;
    float dt = tgt[gp];
    float tmn = __uint_as_float(~g_tminE[v]);
    float st  = __fsub_rn(dt, tmn);
    float trg = __fsub_rn(__uint_as_float(g_tmax[v]), tmn);
    float tn = (trg != 0.f) ? __fdiv_rn(st, trg) : st;
    __stcs(&out[1 + gp], dn);                          // streaming: don't pollute L2
    __stcs(&out[1 + NVW * NPIX + gp], tn);
    float* nout = &out[1 + 2 * NVW * NPIX + 3 * gp];
    if (hit) {
        unsigned lo = (unsigned)(packed & 0xffffffffu);
        int c1 = lo & 0x7f, c2 = (lo >> 7) & 0x7f, c3 = (lo >> 14) & 0x7f;
        float na = 0.f, nb = 0.f, nc = 0.f;            // central-diff normal
        if (c3 >= 1 && c3 <= GD-2 && c2 >= 1 && c2 <= GD-2 && c1 >= 1 && c1 <= GD-2) {
            int base = (c3 * GD + c2) * GD + c1;
            na = __fsub_rn(g_grid[base + 1],     g_grid[base - 1]);
            nb = __fsub_rn(g_grid[base + GD],    g_grid[base - GD]);
            nc = __fsub_rn(g_grid[base + GD*GD], g_grid[base - GD*GD]);
        }
        float rx = dotrow(s_M,     na, nb, nc);
        float ry = dotrow(s_M + 4, na, nb, nc);
        float rz = dotrow(s_M + 8, na, nb, nc);
        float ss = __fadd_rn(__fadd_rn(__fmul_rn(rx, rx), __fmul_rn(ry, ry)),
                             __fmul_rn(rz, rz));
        float len = fmaxf(__fsqrt_rn(ss), 1e-5f);
        __stcs(nout + 0, __fdiv_rn(-rx, len));
        __stcs(nout + 1, __fdiv_rn(-ry, len));
        __stcs(nout + 2, __fdiv_rn(-rz, len));
        g_dz[gp] = 0ull;                               // self-clean
    } else {
        __stcs(nout + 0, 0.f);
        __stcs(nout + 1, 0.f);
        __stcs(nout + 2, 0.f);
    }
    float l = (dt != 0.f) ? fabsf(__fsub_rn(dn, tn)) : 0.f;
    for (int o = 16; o; o >>= 1) l += __shfl_down_sync(0xffffffffu, l, o);
    __shared__ float sl[8];
    int wid = threadIdx.x >> 5, lid = threadIdx.x & 31;
    if (lid == 0) sl[wid] = l;
    __syncthreads();
    if (threadIdx.x == 0) {
        for (int w = 1; w < 8; w++) l += sl[w];
        atomicAdd(&g_lsum[v], l);
    }
}

// --- L4: loss (lanes 0..8 in parallel, one view each) + scalar self-clean ---
__global__ void k_loss(float* __restrict__ out) {
    int lane = threadIdx.x;
    float lv = 0.f;
    if (lane < NVW) {
        float s = g_lsum[lane];
        int   c = g_vcnt[lane];
        float l = (c > 0) ? __fdiv_rn(s, fmaxf((float)c, 1.f)) : 0.f;
        lv = __fdiv_rn(l, 9.0f);                        // * WEIGHT(1) / N_VIEWS
        g_lsum[lane] = 0.f; g_vcnt[lane] = 0;           // self-clean own view
        g_dminE[lane] = 0u; g_tminE[lane] = 0u;
        g_dmax[lane] = 0u;  g_tmax[lane] = 0u;
    }
    for (int o = 16; o; o >>= 1) lv += __shfl_down_sync(0xffffffffu, lv, o);
    if (lane == 0) out[0] = lv;
}

// ---------------------------------------------------------------------------
extern "C" void kernel_launch(void* const* d_in, const int* in_sizes, int n_in,
                              void* d_out, int out_size) {
    const int4*  coords = (const int4*) d_in[0];
    const float* origin = (const float*)d_in[1];
    const float* sdf    = (const float*)d_in[2];
    // d_in[3] = sdf_target (unused by forward)
    const float* tgt    = (const float*)d_in[4];
    const float* intr   = (const float*)d_in[5];
    const float* vm     = (const float*)d_in[6];
    float* out = (float*)d_out;

    int n = in_sizes[0] / 4;
    if (n > MAXN) n = MAXN;
    const int tb = 256;
    int projB = (n + tb - 1) / tb;

    k_point_tmm<<<projB + TMMB, tb>>>(coords, origin, vm, intr, tgt, n, projB);
    k_grid_dmm<<<GRIDB + NVW * DMMV, tb>>>(sdf);
    dim3 rg(PIXB, NVW);
    k_pixel<<<rg, tb>>>(vm, tgt, out);
    k_loss<<<1, 32>>>(out);
}